// round 12
// baseline (speedup 1.0000x reference)
#include <cuda_runtime.h>
#include <math.h>

#define BB  2
#define TT  2048
#define CC  768
#define HH  12
#define HD  64
#define NCH 32
#define CHR 64
#define SCALE 0.125f
#define PT  68    // padded smem pitch: 272B = 17*16B -> LDS.128-aligned rows
#define PA  140   // duplicated-A pitch: 560B, 16B-aligned rows
#define NTRI ((NCH*(NCH+1))/2)   // 528 lower-triangle 64x64 tiles

typedef unsigned long long u64t;

// packed fp32x2 ops
#define FFMA2(c, a, b) asm("fma.rn.f32x2 %0, %1, %2, %0;" : "+l"(c) : "l"(a), "l"(b))
#define FMUL2(c, a)    asm("mul.rn.f32x2 %0, %0, %1;"     : "+l"(c) : "l"(a))
#define PACK2(o, lo, hi) asm("mov.b64 %0, {%1, %2};" : "=l"(o) : "f"(lo), "f"(hi))

__device__ __forceinline__ void unpack2(u64t v, float& lo, float& hi) {
    asm("mov.b64 {%0, %1}, %2;" : "=f"(lo), "=f"(hi) : "l"(v));
}

// ---------------- scratch (static device arrays; no allocs allowed) ---------
__device__ float g_Q [BB*TT*CC];
__device__ float g_K [BB*TT*CC];
__device__ float g_V [BB*TT*CC];
__device__ float g_QS[BB*TT*CC];          // sel_w[h] * q
__device__ float g_S [BB*TT*TT];          // masked selection matrix (lower triangle valid)
__device__ float g_FF[BB*TT*TT];          // exclusive cumsum over rows (valid where needed)
__device__ float g_CS[BB*NCH*TT];         // chunk sums (valid where 64c+63 >= j)
__device__ float g_Y [BB*TT*CC];          // attention output (pre-projection)

// ---- double-buffered GEMM mainloop: one __syncthreads per k-tile -----------
#define GEMM_STORE(P)                                                          \
    do {                                                                       \
        *(float2*)&As2[P][kq+0][2*row] = make_float2(a4.x, a4.x);              \
        *(float2*)&As2[P][kq+1][2*row] = make_float2(a4.y, a4.y);              \
        *(float2*)&As2[P][kq+2][2*row] = make_float2(a4.z, a4.z);              \
        *(float2*)&As2[P][kq+3][2*row] = make_float2(a4.w, a4.w);              \
        Bs[P][kq+0][row]=b4.x; Bs[P][kq+1][row]=b4.y;                          \
        Bs[P][kq+2][row]=b4.z; Bs[P][kq+3][row]=b4.w;                          \
    } while (0)

#define GEMM_MAINLOOP(ARON, BRON)                                              \
    float4 a4 = *(const float4*)(ARON);                                        \
    float4 b4 = *(const float4*)(BRON);                                        \
    int ph = 0;                                                                \
    GEMM_STORE(0);                                                             \
    __syncthreads();                                                           \
    for (int kk = 0; kk < CC; kk += 16) {                                      \
        const bool more = (kk + 16 < CC);                                      \
        if (more) {                                                            \
            a4 = *(const float4*)((ARON) + kk + 16);                           \
            b4 = *(const float4*)((BRON) + kk + 16);                           \
        }                                                                      \
        _Pragma("unroll")                                                      \
        for (int k = 0; k < 16; k++) {                                         \
            ulonglong2 aP0 = *(const ulonglong2*)&As2[ph][k][ty*8];            \
            ulonglong2 aP1 = *(const ulonglong2*)&As2[ph][k][ty*8 + 4];        \
            ulonglong2 bP  = *(const ulonglong2*)&Bs [ph][k][tx*4];            \
            FFMA2(acc2[0][0], aP0.x, bP.x); FFMA2(acc2[0][1], aP0.x, bP.y);    \
            FFMA2(acc2[1][0], aP0.y, bP.x); FFMA2(acc2[1][1], aP0.y, bP.y);    \
            FFMA2(acc2[2][0], aP1.x, bP.x); FFMA2(acc2[2][1], aP1.x, bP.y);    \
            FFMA2(acc2[3][0], aP1.y, bP.x); FFMA2(acc2[3][1], aP1.y, bP.y);    \
        }                                                                      \
        if (more) {                                                            \
            GEMM_STORE(ph ^ 1);                                                \
            ph ^= 1;                                                           \
            __syncthreads();                                                   \
        }                                                                      \
    }

// ---------------- kernel 1: qkv = x @ w_attn^T + b_attn, routed to Q/K/V/QS -
__global__ void __launch_bounds__(256) k_qkv(
    const float* __restrict__ x, const float* __restrict__ w,
    const float* __restrict__ bias, const float* __restrict__ selw)
{
    __shared__ __align__(16) float As2[2][16][PA];
    __shared__ __align__(16) float Bs[2][16][PT];
    const int tx = threadIdx.x, ty = threadIdx.y;
    const int tid = ty*16 + tx;
    const int m0 = blockIdx.y*64, n0 = blockIdx.x*64;
    const int row = tid >> 2, kq = (tid & 3) * 4;
    const float* arow = x + (m0+row)*CC + kq;
    const float* brow = w + (n0+row)*CC + kq;

    u64t acc2[4][2] = {};
    GEMM_MAINLOOP(arow, brow)

    float accf[4][4];
    #pragma unroll
    for (int i2 = 0; i2 < 4; i2++) {
        unpack2(acc2[i2][0], accf[i2][0], accf[i2][1]);
        unpack2(acc2[i2][1], accf[i2][2], accf[i2][3]);
    }
    // which is uniform per block: n0 multiple of 64, boundaries at 768/1536
    const int which = n0 / CC;           // 0=q 1=k 2=v
    const int rem0  = n0 - which*CC;
    const int m     = m0 + ty*4;
    const float4 bias4 = *(const float4*)(bias + n0 + tx*4);
    const float bb4[4] = {bias4.x, bias4.y, bias4.z, bias4.w};
    if (which == 0) {
        const float sw = selw[(rem0 + tx*4) >> 6];   // head spans 64: uniform per quad
        #pragma unroll
        for (int i2 = 0; i2 < 4; i2++) {
            #pragma unroll
            for (int j2 = 0; j2 < 4; j2++) {
                int rem = rem0 + tx*4 + j2;
                float v = accf[i2][j2] + bb4[j2];
                int o = (m+i2)*CC + rem;
                g_Q[o] = v; g_QS[o] = v * sw;
            }
        }
    } else if (which == 1) {
        #pragma unroll
        for (int i2 = 0; i2 < 4; i2++)
            #pragma unroll
            for (int j2 = 0; j2 < 4; j2++)
                g_K[(m+i2)*CC + rem0 + tx*4 + j2] = accf[i2][j2] + bb4[j2];
    } else {
        #pragma unroll
        for (int i2 = 0; i2 < 4; i2++)
            #pragma unroll
            for (int j2 = 0; j2 < 4; j2++)
                g_V[(m+i2)*CC + rem0 + tx*4 + j2] = accf[i2][j2] + bb4[j2];
    }
}

// ---- kernel 2: S tile (lower triangle, compact grid) + fused chunk sums ----
__global__ void __launch_bounds__(256) k_selgemm()
{
    const int b = blockIdx.z;
    const int l = blockIdx.x;
    int iy = (int)((sqrtf(8.f*(float)l + 1.f) - 1.f) * 0.5f);
    while ((iy+1)*(iy+2)/2 <= l) iy++;
    while (iy*(iy+1)/2 > l) iy--;
    const int jx = l - iy*(iy+1)/2;
    const int i0 = iy*64, j0 = jx*64;

    const int tx = threadIdx.x, ty = threadIdx.y;
    float* Sb = g_S + b*TT*TT;

    __shared__ __align__(16) float As2[2][16][PA];
    __shared__ __align__(16) float Bs[2][16][PT];
    __shared__ float cs_sm[16][64];
    const int tid = ty*16+tx;
    const int row = tid >> 2, kq = (tid & 3) * 4;
    const float* arow = g_QS + b*TT*CC + (i0+row)*CC + kq;
    const float* brow = g_K  + b*TT*CC + (j0+row)*CC + kq;

    u64t acc2[4][2] = {};
    GEMM_MAINLOOP(arow, brow)

    float accf[4][4];
    #pragma unroll
    for (int i2 = 0; i2 < 4; i2++) {
        unpack2(acc2[i2][0], accf[i2][0], accf[i2][1]);
        unpack2(acc2[i2][1], accf[i2][2], accf[i2][3]);
    }
    float colp[4] = {0.f, 0.f, 0.f, 0.f};
    #pragma unroll
    for (int i2 = 0; i2 < 4; i2++) {
        int i = i0 + ty*4 + i2;
        #pragma unroll
        for (int j2 = 0; j2 < 4; j2++) {
            int j = j0 + tx*4 + j2;
            float v = accf[i2][j2] * SCALE;
            v = (j >= i || j == 0) ? 0.f : fmaxf(v, 0.f);
            Sb[i*TT + j] = v;
            colp[j2] += v;
        }
    }
    __syncthreads();
    #pragma unroll
    for (int j2 = 0; j2 < 4; j2++) cs_sm[ty][tx*4 + j2] = colp[j2];
    __syncthreads();
    if (tid < 64) {
        float s = 0.f;
        #pragma unroll
        for (int t = 0; t < 16; t++) s += cs_sm[t][tid];
        g_CS[(b*NCH + iy)*TT + j0 + tid] = s;
    }
}

// ---- kernel 3: exclusive scan -> FF_shifted (float4 columns, lower region) -
__global__ void k_scanff()
{
    const int b = blockIdx.z, c = blockIdx.y, bx = blockIdx.x;
    if (64*c + 63 < 1024*bx) return;          // whole block above diagonal: FF never read
    const int j0 = bx*1024 + threadIdx.x*4;   // 4 adjacent columns per thread
    float4 acc = make_float4(0.f, 0.f, 0.f, 0.f);
    for (int cp = (j0 >> 6); cp < c; cp++) {  // cp < j0>>6 have CS==0 for all 4 cols
        float4 cs4 = *(const float4*)(g_CS + (b*NCH + cp)*TT + j0);
        acc.x += cs4.x; acc.y += cs4.y; acc.z += cs4.z; acc.w += cs4.w;
    }
    const float* Sb = g_S  + b*TT*TT + c*CHR*TT;
    float* Fb       = g_FF + b*TT*TT + c*CHR*TT;
    const int rg0 = c*CHR;
    #pragma unroll 4
    for (int r = 0; r < CHR; r++) {
        *(float4*)(Fb + r*TT + j0) = acc;
        const int i = rg0 + r;                // S[r,j] contributes only when i > j
        if (i > j0) {                         // else all 4 predicates false
            float4 s4 = *(const float4*)(Sb + r*TT + j0);
            if (i > j0+0) acc.x += s4.x;
            if (i > j0+1) acc.y += s4.y;
            if (i > j0+2) acc.z += s4.z;
            if (i > j0+3) acc.w += s4.w;
        }
    }
}

// ---------------- kernel 4: flash attention with FF bias (packed fp32x2) ----
// grid (24, 32): bx -> (h, b), by -> it = 31 - by  (global LPT launch order)
__global__ void __launch_bounds__(256) k_attn()
{
    extern __shared__ __align__(16) float sm[];
    float* qsT  = sm;               // [d][i]
    float* ksT  = sm + 64*PT;       // [d][j]
    float* psmT = sm + 2*64*PT;     // [j][i]
    float* vsm  = sm + 3*64*PT;     // [j][d]
    const int h = blockIdx.x % HH, b = blockIdx.x / HH;
    const int it = gridDim.y - 1 - blockIdx.y;   // by=0 -> heaviest tile (it=31)
    const int i0 = it*64;
    const int tid = threadIdx.x;
    const int tx = tid & 15, ty = tid >> 4;
    const float* Qb = g_Q + (b*TT)*CC + h*HD;
    const float* Kb = g_K + (b*TT)*CC + h*HD;
    const float* Vb = g_V + (b*TT)*CC + h*HD;
    const float* Fb = g_FF + b*TT*TT;

    for (int l = tid; l < 1024; l += 256) {
        int i = l >> 4, dq = (l & 15) * 4;
        float4 q4 = *(const float4*)(Qb + (i0+i)*CC + dq);
        qsT[(dq+0)*PT + i] = SCALE*q4.x;
        qsT[(dq+1)*PT + i] = SCALE*q4.y;
        qsT[(dq+2)*PT + i] = SCALE*q4.z;
        qsT[(dq+3)*PT + i] = SCALE*q4.w;
    }
    float m[4], lsum[4];
    u64t o2[4][2];
    #pragma unroll
    for (int u = 0; u < 4; u++) {
        m[u] = -1e30f; lsum[u] = 0.f;
        o2[u][0] = 0ull; o2[u][1] = 0ull;
    }

    for (int jt = 0; jt <= it; jt++) {
        __syncthreads();
        for (int l = tid; l < 1024; l += 256) {
            int j = l >> 4, dq = (l & 15) * 4;
            float4 k4 = *(const float4*)(Kb + (jt*64+j)*CC + dq);
            ksT[(dq+0)*PT + j] = k4.x;
            ksT[(dq+1)*PT + j] = k4.y;
            ksT[(dq+2)*PT + j] = k4.z;
            ksT[(dq+3)*PT + j] = k4.w;
            float4 v4 = *(const float4*)(Vb + (jt*64+j)*CC + dq);
            *(float4*)(vsm + j*PT + dq) = v4;
        }
        __syncthreads();

        // ---- q @ k^T (packed over j pairs) ----
        u64t sc2[4][2] = {};
        const float* qp = qsT + ty*4;
        const float* kp = ksT + tx*4;
        #pragma unroll 8
        for (int d = 0; d < 64; d++) {
            float4 av = *(const float4*)(qp + d*PT);
            ulonglong2 bP = *(const ulonglong2*)(kp + d*PT);
            u64t a0, a1, a2, a3;
            PACK2(a0, av.x, av.x); PACK2(a1, av.y, av.y);
            PACK2(a2, av.z, av.z); PACK2(a3, av.w, av.w);
            FFMA2(sc2[0][0], a0, bP.x); FFMA2(sc2[0][1], a0, bP.y);
            FFMA2(sc2[1][0], a1, bP.x); FFMA2(sc2[1][1], a1, bP.y);
            FFMA2(sc2[2][0], a2, bP.x); FFMA2(sc2[2][1], a2, bP.y);
            FFMA2(sc2[3][0], a3, bP.x); FFMA2(sc2[3][1], a3, bP.y);
        }
        float sc[4][4];
        #pragma unroll
        for (int i2 = 0; i2 < 4; i2++) {
            unpack2(sc2[i2][0], sc[i2][0], sc[i2][1]);
            unpack2(sc2[i2][1], sc[i2][2], sc[i2][3]);
        }
        // subtract FF_shifted, apply causal mask (row-stepped FF pointer)
        const float* fr = Fb + (i0 + ty*4)*TT + jt*64 + tx*4;
        #pragma unroll
        for (int i2 = 0; i2 < 4; i2++, fr += TT) {
            int i = i0 + ty*4 + i2;
            const float4 ff4 = *(const float4*)fr;
            float ff[4] = {ff4.x, ff4.y, ff4.z, ff4.w};
            #pragma unroll
            for (int j2 = 0; j2 < 4; j2++) {
                int j = jt*64 + tx*4 + j2;
                sc[i2][j2] = (j > i) ? -1e30f : (sc[i2][j2] - ff[j2]);
            }
        }
        // online softmax per row
        #pragma unroll
        for (int i2 = 0; i2 < 4; i2++) {
            float tm = fmaxf(fmaxf(sc[i2][0], sc[i2][1]), fmaxf(sc[i2][2], sc[i2][3]));
            #pragma unroll
            for (int mk = 1; mk < 16; mk <<= 1) tm = fmaxf(tm, __shfl_xor_sync(0xffffffffu, tm, mk));
            float mn  = fmaxf(m[i2], tm);
            float fac = __expf(m[i2] - mn);
            float rs  = 0.f;
            #pragma unroll
            for (int j2 = 0; j2 < 4; j2++) {
                float p = __expf(sc[i2][j2] - mn);
                sc[i2][j2] = p;
                rs += p;
            }
            #pragma unroll
            for (int mk = 1; mk < 16; mk <<= 1) rs += __shfl_xor_sync(0xffffffffu, rs, mk);
            lsum[i2] = lsum[i2]*fac + rs;
            m[i2] = mn;
            u64t facP; PACK2(facP, fac, fac);
            FMUL2(o2[i2][0], facP);
            FMUL2(o2[i2][1], facP);
            #pragma unroll
            for (int j2 = 0; j2 < 4; j2++) psmT[(tx*4+j2)*PT + ty*4 + i2] = sc[i2][j2];
        }
        __syncwarp();
        // ---- o += p @ v (packed over d pairs) ----
        const float* pp = psmT + ty*4;
        const float* vp = vsm + tx*4;
        #pragma unroll 8
        for (int j = 0; j < 64; j++) {
            float4 pv4 = *(const float4*)(pp + j*PT);
            ulonglong2 vP = *(const ulonglong2*)(vp + j*PT);
            u64t p0, p1, p2, p3;
            PACK2(p0, pv4.x, pv4.x); PACK2(p1, pv4.y, pv4.y);
            PACK2(p2, pv4.z, pv4.z); PACK2(p3, pv4.w, pv4.w);
            FFMA2(o2[0][0], p0, vP.x); FFMA2(o2[0][1], p0, vP.y);
            FFMA2(o2[1][0], p1, vP.x); FFMA2(o2[1][1], p1, vP.y);
            FFMA2(o2[2][0], p2, vP.x); FFMA2(o2[2][1], p2, vP.y);
            FFMA2(o2[3][0], p3, vP.x); FFMA2(o2[3][1], p3, vP.y);
        }
    }
    float* Yb = g_Y + (b*TT)*CC + h*HD;
    #pragma unroll
    for (int i2 = 0; i2 < 4; i2++) {
        float inv = 1.f / lsum[i2];
        float of[4];
        unpack2(o2[i2][0], of[0], of[1]);
        unpack2(o2[i2][1], of[2], of[3]);
        #pragma unroll
        for (int j2 = 0; j2 < 4; j2++)
            Yb[(i0+ty*4+i2)*CC + tx*4+j2] = of[j2] * inv;
    }
}

// ---------------- kernel 5: out = Y @ w_proj^T + b_proj ---------------------
__global__ void __launch_bounds__(256) k_proj(
    const float* __restrict__ w, const float* __restrict__ bias,
    float* __restrict__ out)
{
    __shared__ __align__(16) float As2[2][16][PA];
    __shared__ __align__(16) float Bs[2][16][PT];
    const int tx = threadIdx.x, ty = threadIdx.y;
    const int tid = ty*16 + tx;
    const int m0 = blockIdx.y*64, n0 = blockIdx.x*64;
    const int row = tid >> 2, kq = (tid & 3) * 4;
    const float* arow = g_Y + (m0+row)*CC + kq;
    const float* brow = w   + (n0+row)*CC + kq;

    u64t acc2[4][2] = {};
    GEMM_MAINLOOP(arow, brow)

    float accf[4][4];
    #pragma unroll
    for (int i2 = 0; i2 < 4; i2++) {
        unpack2(acc2[i2][0], accf[i2][0], accf[i2][1]);
        unpack2(acc2[i2][1], accf[i2][2], accf[i2][3]);
    }
    const float4 bias4 = *(const float4*)(bias + n0 + tx*4);
    const float bb4[4] = {bias4.x, bias4.y, bias4.z, bias4.w};
    #pragma unroll
    for (int i2 = 0; i2 < 4; i2++) {
        int mm = m0 + ty*4 + i2;
        #pragma unroll
        for (int j2 = 0; j2 < 4; j2++)
            out[mm*CC + n0 + tx*4 + j2] = accf[i2][j2] + bb4[j2];
    }
}

// ---------------- launch ----------------------------------------------------
extern "C" void kernel_launch(void* const* d_in, const int* in_sizes, int n_in,
                              void* d_out, int out_size)
{
    const float* x      = (const float*)d_in[0];
    const float* w_attn = (const float*)d_in[1];
    const float* b_attn = (const float*)d_in[2];
    const float* w_proj = (const float*)d_in[3];
    const float* b_proj = (const float*)d_in[4];
    const float* sel_w  = (const float*)d_in[5];
    float* out = (float*)d_out;

    dim3 thr(16, 16);
    k_qkv    <<<dim3(2304/64, (BB*TT)/64), thr>>>(x, w_attn, b_attn, sel_w);
    k_selgemm<<<dim3(NTRI, 1, BB), thr>>>();
    k_scanff <<<dim3(TT/1024, NCH, BB), 256>>>();

    const int smem_attn = 4*64*PT*4;  // 69632 B -> up to 3 CTAs/SM (reg-dependent)
    cudaFuncSetAttribute(k_attn, cudaFuncAttributeMaxDynamicSharedMemorySize, smem_attn);
    k_attn   <<<dim3(HH*BB, TT/64), 256, smem_attn>>>();

    k_proj   <<<dim3(CC/64, (BB*TT)/64), thr>>>(w_proj, b_proj, out);
}

// round 14
// speedup vs baseline: 1.0508x; 1.0508x over previous
#include <cuda_runtime.h>
#include <math.h>

#define BB  2
#define TT  2048
#define CC  768
#define HH  12
#define HD  64
#define NCH 32
#define CHR 64
#define SCALE 0.125f
#define PT  68    // padded smem pitch: 272B = 17*16B -> LDS.128-aligned rows
#define PA  140   // duplicated-A pitch: 560B, 16B-aligned rows
#define NTRI ((NCH*(NCH+1))/2)   // 528 lower-triangle 64x64 tiles

typedef unsigned long long u64t;

// packed fp32x2 ops
#define FFMA2(c, a, b) asm("fma.rn.f32x2 %0, %1, %2, %0;" : "+l"(c) : "l"(a), "l"(b))
#define FMUL2(c, a)    asm("mul.rn.f32x2 %0, %0, %1;"     : "+l"(c) : "l"(a))
#define PACK2(o, lo, hi) asm("mov.b64 %0, {%1, %2};" : "=l"(o) : "f"(lo), "f"(hi))

__device__ __forceinline__ void unpack2(u64t v, float& lo, float& hi) {
    asm("mov.b64 {%0, %1}, %2;" : "=f"(lo), "=f"(hi) : "l"(v));
}

// ---------------- scratch (static device arrays; no allocs allowed) ---------
__device__ float g_QT[BB*HH*HD*TT];       // Q transposed [b][h][d][t] (attn only)
__device__ float g_K [BB*TT*CC];          // K row-major (selgemm)
__device__ float g_KT[BB*HH*HD*TT];       // K transposed [b][h][d][t] (attn)
__device__ float g_V [BB*TT*CC];
__device__ float g_QS[BB*TT*CC];          // sel_w[h] * q (row-major, selgemm)
__device__ float g_S [BB*TT*TT];          // masked selection matrix (lower triangle valid)
__device__ float g_FF[BB*TT*TT];          // exclusive cumsum over rows (valid where needed)
__device__ float g_CS[BB*NCH*TT];         // chunk sums (valid where 64c+63 >= j)
__device__ float g_Y [BB*TT*CC];          // attention output (pre-projection)

// ---- double-buffered GEMM mainloop: one __syncthreads per k-tile -----------
#define GEMM_STORE(P)                                                          \
    do {                                                                       \
        *(float2*)&As2[P][kq+0][2*row] = make_float2(a4.x, a4.x);              \
        *(float2*)&As2[P][kq+1][2*row] = make_float2(a4.y, a4.y);              \
        *(float2*)&As2[P][kq+2][2*row] = make_float2(a4.z, a4.z);              \
        *(float2*)&As2[P][kq+3][2*row] = make_float2(a4.w, a4.w);              \
        Bs[P][kq+0][row]=b4.x; Bs[P][kq+1][row]=b4.y;                          \
        Bs[P][kq+2][row]=b4.z; Bs[P][kq+3][row]=b4.w;                          \
    } while (0)

#define GEMM_MAINLOOP(ARON, BRON)                                              \
    float4 a4 = *(const float4*)(ARON);                                        \
    float4 b4 = *(const float4*)(BRON);                                        \
    int ph = 0;                                                                \
    GEMM_STORE(0);                                                             \
    __syncthreads();                                                           \
    for (int kk = 0; kk < CC; kk += 16) {                                      \
        const bool more = (kk + 16 < CC);                                      \
        if (more) {                                                            \
            a4 = *(const float4*)((ARON) + kk + 16);                           \
            b4 = *(const float4*)((BRON) + kk + 16);                           \
        }                                                                      \
        _Pragma("unroll")                                                      \
        for (int k = 0; k < 16; k++) {                                         \
            ulonglong2 aP0 = *(const ulonglong2*)&As2[ph][k][ty*8];            \
            ulonglong2 aP1 = *(const ulonglong2*)&As2[ph][k][ty*8 + 4];        \
            ulonglong2 bP  = *(const ulonglong2*)&Bs [ph][k][tx*4];            \
            FFMA2(acc2[0][0], aP0.x, bP.x); FFMA2(acc2[0][1], aP0.x, bP.y);    \
            FFMA2(acc2[1][0], aP0.y, bP.x); FFMA2(acc2[1][1], aP0.y, bP.y);    \
            FFMA2(acc2[2][0], aP1.x, bP.x); FFMA2(acc2[2][1], aP1.x, bP.y);    \
            FFMA2(acc2[3][0], aP1.y, bP.x); FFMA2(acc2[3][1], aP1.y, bP.y);    \
        }                                                                      \
        if (more) {                                                            \
            GEMM_STORE(ph ^ 1);                                                \
            ph ^= 1;                                                           \
            __syncthreads();                                                   \
        }                                                                      \
    }

// ---------------- kernel 1: qkv = x @ w_attn^T + b_attn, routed -------------
__global__ void __launch_bounds__(256) k_qkv(
    const float* __restrict__ x, const float* __restrict__ w,
    const float* __restrict__ bias, const float* __restrict__ selw)
{
    __shared__ __align__(16) float As2[2][16][PA];
    __shared__ __align__(16) float Bs[2][16][PT];
    const int tx = threadIdx.x, ty = threadIdx.y;
    const int tid = ty*16 + tx;
    const int m0 = blockIdx.y*64, n0 = blockIdx.x*64;
    const int row = tid >> 2, kq = (tid & 3) * 4;
    const float* arow = x + (m0+row)*CC + kq;
    const float* brow = w + (n0+row)*CC + kq;

    u64t acc2[4][2] = {};
    GEMM_MAINLOOP(arow, brow)

    float accf[4][4];
    #pragma unroll
    for (int i2 = 0; i2 < 4; i2++) {
        unpack2(acc2[i2][0], accf[i2][0], accf[i2][1]);
        unpack2(acc2[i2][1], accf[i2][2], accf[i2][3]);
    }
    // which is uniform per block: n0 multiple of 64, boundaries at 768/1536
    const int which = n0 / CC;           // 0=q 1=k 2=v
    const int rem0  = n0 - which*CC;
    const int m     = m0 + ty*4;
    const float4 bias4 = *(const float4*)(bias + n0 + tx*4);
    const float bb4[4] = {bias4.x, bias4.y, bias4.z, bias4.w};
    const int bq = m0 >> 11;                       // batch (TT=2048)
    const int h0 = (rem0 + tx*4) >> 6;             // head (quad never crosses)
    const int d0 = (rem0 + tx*4) & 63;
    const int t0 = m0 - bq*TT + ty*4;

    float vals[4][4];
    #pragma unroll
    for (int i2 = 0; i2 < 4; i2++)
        #pragma unroll
        for (int j2 = 0; j2 < 4; j2++)
            vals[i2][j2] = accf[i2][j2] + bb4[j2];

    if (which == 0) {
        const float sw = selw[h0];
        float* qt = g_QT + ((bq*HH + h0)*HD + d0)*TT + t0;
        #pragma unroll
        for (int i2 = 0; i2 < 4; i2++)
            *(float4*)(g_QS + (m+i2)*CC + rem0 + tx*4) = make_float4(
                vals[i2][0]*sw, vals[i2][1]*sw, vals[i2][2]*sw, vals[i2][3]*sw);
        #pragma unroll
        for (int j2 = 0; j2 < 4; j2++)
            *(float4*)(qt + j2*TT) = make_float4(
                vals[0][j2], vals[1][j2], vals[2][j2], vals[3][j2]);
    } else if (which == 1) {
        float* kt = g_KT + ((bq*HH + h0)*HD + d0)*TT + t0;
        #pragma unroll
        for (int i2 = 0; i2 < 4; i2++)
            *(float4*)(g_K + (m+i2)*CC + rem0 + tx*4) = make_float4(
                vals[i2][0], vals[i2][1], vals[i2][2], vals[i2][3]);
        #pragma unroll
        for (int j2 = 0; j2 < 4; j2++)
            *(float4*)(kt + j2*TT) = make_float4(
                vals[0][j2], vals[1][j2], vals[2][j2], vals[3][j2]);
    } else {
        #pragma unroll
        for (int i2 = 0; i2 < 4; i2++)
            *(float4*)(g_V + (m+i2)*CC + rem0 + tx*4) = make_float4(
                vals[i2][0], vals[i2][1], vals[i2][2], vals[i2][3]);
    }
}

// ---- kernel 2: S tile (lower triangle, compact grid) + fused chunk sums ----
__global__ void __launch_bounds__(256) k_selgemm()
{
    const int b = blockIdx.z;
    const int l = blockIdx.x;
    int iy = (int)((sqrtf(8.f*(float)l + 1.f) - 1.f) * 0.5f);
    while ((iy+1)*(iy+2)/2 <= l) iy++;
    while (iy*(iy+1)/2 > l) iy--;
    const int jx = l - iy*(iy+1)/2;
    const int i0 = iy*64, j0 = jx*64;

    const int tx = threadIdx.x, ty = threadIdx.y;
    float* Sb = g_S + b*TT*TT;

    __shared__ __align__(16) float As2[2][16][PA];
    __shared__ __align__(16) float Bs[2][16][PT];
    __shared__ float cs_sm[16][64];
    const int tid = ty*16+tx;
    const int row = tid >> 2, kq = (tid & 3) * 4;
    const float* arow = g_QS + b*TT*CC + (i0+row)*CC + kq;
    const float* brow = g_K  + b*TT*CC + (j0+row)*CC + kq;

    u64t acc2[4][2] = {};
    GEMM_MAINLOOP(arow, brow)

    float accf[4][4];
    #pragma unroll
    for (int i2 = 0; i2 < 4; i2++) {
        unpack2(acc2[i2][0], accf[i2][0], accf[i2][1]);
        unpack2(acc2[i2][1], accf[i2][2], accf[i2][3]);
    }
    float colp[4] = {0.f, 0.f, 0.f, 0.f};
    #pragma unroll
    for (int i2 = 0; i2 < 4; i2++) {
        int i = i0 + ty*4 + i2;
        float sv[4];
        #pragma unroll
        for (int j2 = 0; j2 < 4; j2++) {
            int j = j0 + tx*4 + j2;
            float v = accf[i2][j2] * SCALE;
            v = (j >= i || j == 0) ? 0.f : fmaxf(v, 0.f);
            sv[j2] = v;
            colp[j2] += v;
        }
        *(float4*)(Sb + i*TT + j0 + tx*4) = make_float4(sv[0], sv[1], sv[2], sv[3]);
    }
    __syncthreads();
    #pragma unroll
    for (int j2 = 0; j2 < 4; j2++) cs_sm[ty][tx*4 + j2] = colp[j2];
    __syncthreads();
    if (tid < 64) {
        float s = 0.f;
        #pragma unroll
        for (int t = 0; t < 16; t++) s += cs_sm[t][tid];
        g_CS[(b*NCH + iy)*TT + j0 + tid] = s;
    }
}

// ---- kernel 3: exclusive scan -> FF_shifted (float4 columns, lower region) -
__global__ void k_scanff()
{
    const int b = blockIdx.z, c = blockIdx.y, bx = blockIdx.x;
    if (64*c + 63 < 1024*bx) return;          // whole block above diagonal: FF never read
    const int j0 = bx*1024 + threadIdx.x*4;   // 4 adjacent columns per thread
    float4 acc = make_float4(0.f, 0.f, 0.f, 0.f);
    for (int cp = (j0 >> 6); cp < c; cp++) {  // cp < j0>>6 have CS==0 for all 4 cols
        float4 cs4 = *(const float4*)(g_CS + (b*NCH + cp)*TT + j0);
        acc.x += cs4.x; acc.y += cs4.y; acc.z += cs4.z; acc.w += cs4.w;
    }
    const float* Sb = g_S  + b*TT*TT + c*CHR*TT;
    float* Fb       = g_FF + b*TT*TT + c*CHR*TT;
    const int rg0 = c*CHR;
    #pragma unroll 4
    for (int r = 0; r < CHR; r++) {
        *(float4*)(Fb + r*TT + j0) = acc;
        const int i = rg0 + r;                // S[r,j] contributes only when i > j
        if (i > j0) {                         // else all 4 predicates false
            float4 s4 = *(const float4*)(Sb + r*TT + j0);
            if (i > j0+0) acc.x += s4.x;
            if (i > j0+1) acc.y += s4.y;
            if (i > j0+2) acc.z += s4.z;
            if (i > j0+3) acc.w += s4.w;
        }
    }
}

// ---------------- kernel 4: flash attention with FF bias (packed fp32x2) ----
// grid (24, 32): bx -> (h, b), by -> it = 31 - by  (global LPT launch order)
__global__ void __launch_bounds__(256) k_attn()
{
    extern __shared__ __align__(16) float sm[];
    float* qsT = sm;               // [d][i]
    float* ksT = sm + 64*PT;       // [d][j]
    float* psm = sm + 2*64*PT;     // [i][j]  (row-major p; conflict-free STS.128)
    float* vsm = sm + 3*64*PT;     // [j][d]
    const int h = blockIdx.x % HH, b = blockIdx.x / HH;
    const int it = gridDim.y - 1 - blockIdx.y;   // by=0 -> heaviest tile (it=31)
    const int i0 = it*64;
    const int tid = threadIdx.x;
    const int tx = tid & 15, ty = tid >> 4;
    const float* QTb = g_QT + (b*HH + h)*HD*TT;  // [d][t]
    const float* KTb = g_KT + (b*HH + h)*HD*TT;  // [d][t]
    const float* Vb  = g_V + (b*TT)*CC + h*HD;
    const float* Fb  = g_FF + b*TT*TT;

    // q tile fill: contiguous LDG.128 -> conflict-free STS.128
    for (int l = tid; l < 1024; l += 256) {
        int d = l >> 4, iq = (l & 15) * 4;
        float4 q4 = *(const float4*)(QTb + d*TT + i0 + iq);
        *(float4*)(qsT + d*PT + iq) =
            make_float4(SCALE*q4.x, SCALE*q4.y, SCALE*q4.z, SCALE*q4.w);
    }
    float m[4], lsum[4];
    u64t o2[4][2];
    #pragma unroll
    for (int u = 0; u < 4; u++) {
        m[u] = -1e30f; lsum[u] = 0.f;
        o2[u][0] = 0ull; o2[u][1] = 0ull;
    }

    for (int jt = 0; jt <= it; jt++) {
        __syncthreads();
        // k/v tile fill: contiguous both sides, conflict-free
        for (int l = tid; l < 1024; l += 256) {
            int r = l >> 4, cq = (l & 15) * 4;
            *(float4*)(ksT + r*PT + cq) = *(const float4*)(KTb + r*TT + jt*64 + cq);
            *(float4*)(vsm + r*PT + cq) = *(const float4*)(Vb + (jt*64+r)*CC + cq);
        }
        __syncthreads();

        // ---- q @ k^T (packed over j pairs) ----
        u64t sc2[4][2] = {};
        const float* qp = qsT + ty*4;
        const float* kp = ksT + tx*4;
        #pragma unroll 8
        for (int d = 0; d < 64; d++) {
            float4 av = *(const float4*)(qp + d*PT);
            ulonglong2 bP = *(const ulonglong2*)(kp + d*PT);
            u64t a0, a1, a2, a3;
            PACK2(a0, av.x, av.x); PACK2(a1, av.y, av.y);
            PACK2(a2, av.z, av.z); PACK2(a3, av.w, av.w);
            FFMA2(sc2[0][0], a0, bP.x); FFMA2(sc2[0][1], a0, bP.y);
            FFMA2(sc2[1][0], a1, bP.x); FFMA2(sc2[1][1], a1, bP.y);
            FFMA2(sc2[2][0], a2, bP.x); FFMA2(sc2[2][1], a2, bP.y);
            FFMA2(sc2[3][0], a3, bP.x); FFMA2(sc2[3][1], a3, bP.y);
        }
        float sc[4][4];
        #pragma unroll
        for (int i2 = 0; i2 < 4; i2++) {
            unpack2(sc2[i2][0], sc[i2][0], sc[i2][1]);
            unpack2(sc2[i2][1], sc[i2][2], sc[i2][3]);
        }
        // subtract FF_shifted, apply causal mask (row-stepped FF pointer)
        const float* fr = Fb + (i0 + ty*4)*TT + jt*64 + tx*4;
        #pragma unroll
        for (int i2 = 0; i2 < 4; i2++, fr += TT) {
            int i = i0 + ty*4 + i2;
            const float4 ff4 = *(const float4*)fr;
            float ff[4] = {ff4.x, ff4.y, ff4.z, ff4.w};
            #pragma unroll
            for (int j2 = 0; j2 < 4; j2++) {
                int j = jt*64 + tx*4 + j2;
                sc[i2][j2] = (j > i) ? -1e30f : (sc[i2][j2] - ff[j2]);
            }
        }
        // online softmax per row; store p ROW-major (conflict-free STS.128)
        #pragma unroll
        for (int i2 = 0; i2 < 4; i2++) {
            float tm = fmaxf(fmaxf(sc[i2][0], sc[i2][1]), fmaxf(sc[i2][2], sc[i2][3]));
            #pragma unroll
            for (int mk = 1; mk < 16; mk <<= 1) tm = fmaxf(tm, __shfl_xor_sync(0xffffffffu, tm, mk));
            float mn  = fmaxf(m[i2], tm);
            float fac = __expf(m[i2] - mn);
            float rs  = 0.f;
            #pragma unroll
            for (int j2 = 0; j2 < 4; j2++) {
                float p = __expf(sc[i2][j2] - mn);
                sc[i2][j2] = p;
                rs += p;
            }
            #pragma unroll
            for (int mk = 1; mk < 16; mk <<= 1) rs += __shfl_xor_sync(0xffffffffu, rs, mk);
            lsum[i2] = lsum[i2]*fac + rs;
            m[i2] = mn;
            u64t facP; PACK2(facP, fac, fac);
            FMUL2(o2[i2][0], facP);
            FMUL2(o2[i2][1], facP);
            *(float4*)(psm + (ty*4+i2)*PT + tx*4) =
                make_float4(sc[i2][0], sc[i2][1], sc[i2][2], sc[i2][3]);
        }
        __syncwarp();
        // ---- o += p @ v: p read row-major (own rows), v in 4-row blocks ----
        // accumulation order identical to j-ascending (jg outer, j2 inner)
        const float* pr = psm + (ty*4)*PT;
        const float* vp = vsm + tx*4;
        #pragma unroll 4
        for (int jg = 0; jg < 16; jg++) {
            float4 p0 = *(const float4*)(pr + 0*PT + jg*4);
            float4 p1 = *(const float4*)(pr + 1*PT + jg*4);
            float4 p2 = *(const float4*)(pr + 2*PT + jg*4);
            float4 p3 = *(const float4*)(pr + 3*PT + jg*4);
            ulonglong2 v0 = *(const ulonglong2*)(vp + (jg*4+0)*PT);
            ulonglong2 v1 = *(const ulonglong2*)(vp + (jg*4+1)*PT);
            ulonglong2 v2 = *(const ulonglong2*)(vp + (jg*4+2)*PT);
            ulonglong2 v3 = *(const ulonglong2*)(vp + (jg*4+3)*PT);
            u64t pk;
            PACK2(pk, p0.x, p0.x); FFMA2(o2[0][0], pk, v0.x); FFMA2(o2[0][1], pk, v0.y);
            PACK2(pk, p1.x, p1.x); FFMA2(o2[1][0], pk, v0.x); FFMA2(o2[1][1], pk, v0.y);
            PACK2(pk, p2.x, p2.x); FFMA2(o2[2][0], pk, v0.x); FFMA2(o2[2][1], pk, v0.y);
            PACK2(pk, p3.x, p3.x); FFMA2(o2[3][0], pk, v0.x); FFMA2(o2[3][1], pk, v0.y);
            PACK2(pk, p0.y, p0.y); FFMA2(o2[0][0], pk, v1.x); FFMA2(o2[0][1], pk, v1.y);
            PACK2(pk, p1.y, p1.y); FFMA2(o2[1][0], pk, v1.x); FFMA2(o2[1][1], pk, v1.y);
            PACK2(pk, p2.y, p2.y); FFMA2(o2[2][0], pk, v1.x); FFMA2(o2[2][1], pk, v1.y);
            PACK2(pk, p3.y, p3.y); FFMA2(o2[3][0], pk, v1.x); FFMA2(o2[3][1], pk, v1.y);
            PACK2(pk, p0.z, p0.z); FFMA2(o2[0][0], pk, v2.x); FFMA2(o2[0][1], pk, v2.y);
            PACK2(pk, p1.z, p1.z); FFMA2(o2[1][0], pk, v2.x); FFMA2(o2[1][1], pk, v2.y);
            PACK2(pk, p2.z, p2.z); FFMA2(o2[2][0], pk, v2.x); FFMA2(o2[2][1], pk, v2.y);
            PACK2(pk, p3.z, p3.z); FFMA2(o2[3][0], pk, v2.x); FFMA2(o2[3][1], pk, v2.y);
            PACK2(pk, p0.w, p0.w); FFMA2(o2[0][0], pk, v3.x); FFMA2(o2[0][1], pk, v3.y);
            PACK2(pk, p1.w, p1.w); FFMA2(o2[1][0], pk, v3.x); FFMA2(o2[1][1], pk, v3.y);
            PACK2(pk, p2.w, p2.w); FFMA2(o2[2][0], pk, v3.x); FFMA2(o2[2][1], pk, v3.y);
            PACK2(pk, p3.w, p3.w); FFMA2(o2[3][0], pk, v3.x); FFMA2(o2[3][1], pk, v3.y);
        }
    }
    float* Yb = g_Y + (b*TT)*CC + h*HD;
    #pragma unroll
    for (int i2 = 0; i2 < 4; i2++) {
        float inv = 1.f / lsum[i2];
        float of[4];
        unpack2(o2[i2][0], of[0], of[1]);
        unpack2(o2[i2][1], of[2], of[3]);
        *(float4*)(Yb + (i0+ty*4+i2)*CC + tx*4) =
            make_float4(of[0]*inv, of[1]*inv, of[2]*inv, of[3]*inv);
    }
}

// ---------------- kernel 5: out = Y @ w_proj^T + b_proj ---------------------
__global__ void __launch_bounds__(256) k_proj(
    const float* __restrict__ w, const float* __restrict__ bias,
    float* __restrict__ out)
{
    __shared__ __align__(16) float As2[2][16][PA];
    __shared__ __align__(16) float Bs[2][16][PT];
    const int tx = threadIdx.x, ty = threadIdx.y;
    const int tid = ty*16 + tx;
    const int m0 = blockIdx.y*64, n0 = blockIdx.x*64;
    const int row = tid >> 2, kq = (tid & 3) * 4;
    const float* arow = g_Y + (m0+row)*CC + kq;
    const float* brow = w   + (n0+row)*CC + kq;

    u64t acc2[4][2] = {};
    GEMM_MAINLOOP(arow, brow)

    float accf[4][4];
    #pragma unroll
    for (int i2 = 0; i2 < 4; i2++) {
        unpack2(acc2[i2][0], accf[i2][0], accf[i2][1]);
        unpack2(acc2[i2][1], accf[i2][2], accf[i2][3]);
    }
    const float4 bias4 = *(const float4*)(bias + n0 + tx*4);
    #pragma unroll
    for (int i2 = 0; i2 < 4; i2++) {
        int mm = m0 + ty*4 + i2;
        *(float4*)(out + mm*CC + n0 + tx*4) = make_float4(
            accf[i2][0] + bias4.x, accf[i2][1] + bias4.y,
            accf[i2][2] + bias4.z, accf[i2][3] + bias4.w);
    }
}

// ---------------- launch ----------------------------------------------------
extern "C" void kernel_launch(void* const* d_in, const int* in_sizes, int n_in,
                              void* d_out, int out_size)
{
    const float* x      = (const float*)d_in[0];
    const float* w_attn = (const float*)d_in[1];
    const float* b_attn = (const float*)d_in[2];
    const float* w_proj = (const float*)d_in[3];
    const float* b_proj = (const float*)d_in[4];
    const float* sel_w  = (const float*)d_in[5];
    float* out = (float*)d_out;

    dim3 thr(16, 16);
    k_qkv    <<<dim3(2304/64, (BB*TT)/64), thr>>>(x, w_attn, b_attn, sel_w);
    k_selgemm<<<dim3(NTRI, 1, BB), thr>>>();
    k_scanff <<<dim3(TT/1024, NCH, BB), 256>>>();

    const int smem_attn = 4*64*PT*4;  // 69632 B -> 3 CTAs/SM @78 regs
    cudaFuncSetAttribute(k_attn, cudaFuncAttributeMaxDynamicSharedMemorySize, smem_attn);
    k_attn   <<<dim3(HH*BB, TT/64), 256, smem_attn>>>();

    k_proj   <<<dim3(CC/64, (BB*TT)/64), thr>>>(w_proj, b_proj, out);
}